// round 2
// baseline (speedup 1.0000x reference)
#include <cuda_runtime.h>
#include <cuda_bf16.h>
#include <math.h>

// ---------------------------------------------------------------------------
// Problem shape (fixed by the reference): B=4, S=1024, D=1024, H=16, HD=64, F=4096
// ---------------------------------------------------------------------------
static constexpr int Bc = 4;
static constexpr int Sc = 1024;
static constexpr int Dc = 1024;
static constexpr int Hc = 16;
static constexpr int HDc = 64;
static constexpr int Fc = 4096;
static constexpr int Mrows = Bc * Sc;          // 4096
static constexpr long long SD = (long long)Sc * Dc;

// ---------------------------------------------------------------------------
// Scratch (static __device__ arrays -> no allocation, graph-capture safe)
// ---------------------------------------------------------------------------
__device__ float g_h   [Mrows * Dc];                  // LN output (reused for LN2)
__device__ float g_q   [Mrows * Dc];
__device__ float g_k   [Mrows * Dc];
__device__ float g_v   [Mrows * Dc];
__device__ float g_sc  [(long long)Bc * Hc * Sc * Sc]; // 256 MB scores
__device__ float g_attn[Mrows * Dc];
__device__ float g_x1  [Mrows * Dc];
__device__ float g_ff1 [Mrows * Fc];                  // 64 MB
__device__ float g_maskbias[Bc * Sc];                 // normalized mask: 0 or -3e38

// ---------------------------------------------------------------------------
// Mask normalization. The harness may encode the bool mask as int32, float32,
// or raw bool bytes. Detect on-device (reading only within the smallest
// possible buffer extent), then write an additive bias per (b, key).
// ---------------------------------------------------------------------------
__global__ void mask_prep_kernel(const unsigned char* __restrict__ m,
                                 float* __restrict__ bias) {
    __shared__ int s_not_i32;
    __shared__ int s_not_f32;
    if (threadIdx.x == 0) { s_not_i32 = 0; s_not_f32 = 0; }
    __syncthreads();

    // Scan only the first Bc*Sc bytes (valid under every encoding).
    // int32 encoding: bytes at offsets %4 != 0 are all zero.
    for (int i = threadIdx.x; i < Bc * Sc; i += blockDim.x) {
        if ((i & 3) != 0 && m[i] != 0) s_not_i32 = 1;   // benign race: writes 1 only
    }
    // float32 encoding: every 32-bit word is 0.0f or 1.0f.
    const unsigned int* w = (const unsigned int*)m;
    for (int i = threadIdx.x; i < (Bc * Sc) / 4; i += blockDim.x) {
        unsigned int x = w[i];
        if (x != 0u && x != 0x3F800000u) s_not_f32 = 1;
    }
    __syncthreads();

    const bool is_i32 = !s_not_i32;
    const bool is_f32 = !is_i32 && !s_not_f32;

    for (int i = threadIdx.x; i < Bc * Sc; i += blockDim.x) {
        int mv;
        if (is_i32)      mv = ((const int*)m)[i];
        else if (is_f32) mv = (((const unsigned int*)m)[i] != 0u);
        else             mv = (int)m[i];
        bias[i] = mv ? -3.0e38f : 0.0f;
    }
}

// ---------------------------------------------------------------------------
// Reductions
// ---------------------------------------------------------------------------
__device__ __forceinline__ float warp_sum(float v) {
    #pragma unroll
    for (int o = 16; o > 0; o >>= 1) v += __shfl_xor_sync(0xFFFFFFFFu, v, o);
    return v;
}
__device__ __forceinline__ float warp_max(float v) {
    #pragma unroll
    for (int o = 16; o > 0; o >>= 1) v = fmaxf(v, __shfl_xor_sync(0xFFFFFFFFu, v, o));
    return v;
}

// ---------------------------------------------------------------------------
// LayerNorm: one block (256 threads) per row of 1024
// ---------------------------------------------------------------------------
__global__ void ln_kernel(const float* __restrict__ x,
                          const float* __restrict__ g,
                          const float* __restrict__ beta,
                          float* __restrict__ y) {
    const int row = blockIdx.x;
    const float* xr = x + (size_t)row * Dc;
    float v[4], s = 0.f, sq = 0.f;
    #pragma unroll
    for (int i = 0; i < 4; i++) {
        float t = xr[threadIdx.x + i * 256];
        v[i] = t; s += t; sq += t * t;
    }
    __shared__ float sh[2][8];
    s = warp_sum(s); sq = warp_sum(sq);
    const int wid = threadIdx.x >> 5, lid = threadIdx.x & 31;
    if (lid == 0) { sh[0][wid] = s; sh[1][wid] = sq; }
    __syncthreads();
    if (wid == 0) {
        float a  = (lid < 8) ? sh[0][lid] : 0.f;
        float b2 = (lid < 8) ? sh[1][lid] : 0.f;
        a = warp_sum(a); b2 = warp_sum(b2);
        if (lid == 0) { sh[0][0] = a; sh[1][0] = b2; }
    }
    __syncthreads();
    const float mu   = sh[0][0] * (1.f / Dc);
    const float var  = sh[1][0] * (1.f / Dc) - mu * mu;
    const float rstd = rsqrtf(var + 1e-5f);
    float* yr = y + (size_t)row * Dc;
    #pragma unroll
    for (int i = 0; i < 4; i++) {
        int c = threadIdx.x + i * 256;
        yr[c] = (v[i] - mu) * rstd * g[c] + beta[c];
    }
}

// ---------------------------------------------------------------------------
// Softmax over keys with additive mask bias (0 or -3e38 per (b,key)).
// One block per (b,h,q) row of 1024 scores.
// ---------------------------------------------------------------------------
__global__ void softmax_kernel(float* __restrict__ sc,
                               const float* __restrict__ maskbias) {
    const long long row = blockIdx.x;                  // 0 .. B*H*S-1
    const int b = (int)(row / ((long long)Hc * Sc));
    float* p = sc + row * Sc;
    const float* mrow = maskbias + (size_t)b * Sc;

    float v[4], mx = -3.0e38f;
    #pragma unroll
    for (int i = 0; i < 4; i++) {
        int c = threadIdx.x + i * 256;
        float t = p[c] + mrow[c];
        v[i] = t; mx = fmaxf(mx, t);
    }
    __shared__ float sh[8];
    mx = warp_max(mx);
    const int wid = threadIdx.x >> 5, lid = threadIdx.x & 31;
    if (lid == 0) sh[wid] = mx;
    __syncthreads();
    if (wid == 0) {
        float a = (lid < 8) ? sh[lid] : -3.0e38f;
        a = warp_max(a);
        if (lid == 0) sh[0] = a;
    }
    __syncthreads();
    const float M = sh[0];

    float s = 0.f;
    #pragma unroll
    for (int i = 0; i < 4; i++) {
        float e = (v[i] <= -1.0e38f) ? 0.f : __expf(v[i] - M);
        v[i] = e; s += e;
    }
    __syncthreads();
    s = warp_sum(s);
    if (lid == 0) sh[wid] = s;
    __syncthreads();
    if (wid == 0) {
        float a = (lid < 8) ? sh[lid] : 0.f;
        a = warp_sum(a);
        if (lid == 0) sh[0] = a;
    }
    __syncthreads();
    const float inv = 1.f / sh[0];
    #pragma unroll
    for (int i = 0; i < 4; i++) {
        int c = threadIdx.x + i * 256;
        p[c] = v[i] * inv;
    }
}

// ---------------------------------------------------------------------------
// Generic tiled SGEMM with fused epilogues.
//   C = epilogue( A @ B(^T) )
// EPI: 0 = +bias ; 1 = +bias +residual ; 2 = +bias, exact-erf GELU ;
//      3 = alpha*acc + relative position bias (scores)
// MODE: 0 = plain (gridDim.z==1)
//       1 = attention scores: z=(b*H+h); A=Q[b,:,h*HD..], B=K same, C=scores[z]
//       2 = attn@V:           z=(b*H+h); A=scores[z], B=V[b,:,h*HD..], C=attn[b,:,h*HD..]
// ---------------------------------------------------------------------------
__device__ __forceinline__ float gelu_exact(float x) {
    return 0.5f * x * (1.0f + erff(x * 0.7071067811865475f));
}

template<int BM, int BN, int BK, int TM, int TN, bool TRANSB, int EPI, int MODE>
__global__ void gemm_kernel(const float* __restrict__ A,
                            const float* __restrict__ Bm,
                            const float* __restrict__ bias,
                            const float* __restrict__ res,
                            float* __restrict__ C,
                            int Mdim, int Ndim, int Kdim,
                            int lda, int ldb, int ldc,
                            float alpha) {
    constexpr int NT = (BM / TM) * (BN / TN);
    const int tid  = threadIdx.x;
    const int row0 = blockIdx.y * BM;
    const int col0 = blockIdx.x * BN;
    const int z    = blockIdx.z;

    const float* Ap = A;
    const float* Bp = Bm;
    float* Cp = C;
    const float* Rp = res;

    if (MODE == 1) {
        const int b = z / Hc, h = z % Hc;
        Ap += (long long)b * SD + h * HDc;
        Bp += (long long)b * SD + h * HDc;
        Cp += (long long)z * Sc * Sc;
    } else if (MODE == 2) {
        const int b = z / Hc, h = z % Hc;
        Ap += (long long)z * Sc * Sc;
        Bp += (long long)b * SD + h * HDc;
        Cp += (long long)b * SD + h * HDc;
    }

    __shared__ float As[BK][BM];
    __shared__ float Bs[BK][BN];

    float acc[TM][TN];
    #pragma unroll
    for (int i = 0; i < TM; i++)
        #pragma unroll
        for (int j = 0; j < TN; j++) acc[i][j] = 0.f;

    const int ty = tid / (BN / TN);
    const int tx = tid % (BN / TN);

    for (int k0 = 0; k0 < Kdim; k0 += BK) {
        // --- load A tile (BM x BK) ---
        #pragma unroll 4
        for (int i = tid; i < BM * BK; i += NT) {
            const int r = i / BK, c = i % BK;
            const int gr = row0 + r, gk = k0 + c;
            As[c][r] = (gr < Mdim && gk < Kdim) ? Ap[(size_t)gr * lda + gk] : 0.f;
        }
        // --- load B tile (BK x BN) ---
        if (TRANSB) {
            #pragma unroll 4
            for (int i = tid; i < BK * BN; i += NT) {
                const int n = i / BK, c = i % BK;
                const int gk = k0 + c, gn = col0 + n;
                Bs[c][n] = (gk < Kdim && gn < Ndim) ? Bp[(size_t)gn * ldb + gk] : 0.f;
            }
        } else {
            #pragma unroll 4
            for (int i = tid; i < BK * BN; i += NT) {
                const int c = i / BN, n = i % BN;
                const int gk = k0 + c, gn = col0 + n;
                Bs[c][n] = (gk < Kdim && gn < Ndim) ? Bp[(size_t)gk * ldb + gn] : 0.f;
            }
        }
        __syncthreads();

        #pragma unroll
        for (int kk = 0; kk < BK; kk++) {
            float ra[TM], rb[TN];
            #pragma unroll
            for (int i = 0; i < TM; i++) ra[i] = As[kk][ty * TM + i];
            #pragma unroll
            for (int j = 0; j < TN; j++) rb[j] = Bs[kk][tx * TN + j];
            #pragma unroll
            for (int i = 0; i < TM; i++)
                #pragma unroll
                for (int j = 0; j < TN; j++)
                    acc[i][j] = fmaf(ra[i], rb[j], acc[i][j]);
        }
        __syncthreads();
    }

    // --- epilogue ---
    #pragma unroll
    for (int i = 0; i < TM; i++) {
        const int gm = row0 + ty * TM + i;
        if (gm >= Mdim) continue;
        #pragma unroll
        for (int j = 0; j < TN; j++) {
            const int gn = col0 + tx * TN + j;
            if (gn >= Ndim) continue;
            float v = acc[i][j];
            if (EPI == 3) {
                v = v * alpha - 0.1f * fabsf((float)(gm - gn));
            } else {
                if (bias) v += bias[gn];
                if (EPI == 2) v = gelu_exact(v);
                if (EPI == 1) v += Rp[(size_t)gm * ldc + gn];
            }
            Cp[(size_t)gm * ldc + gn] = v;
        }
    }
}

// ---------------------------------------------------------------------------
// Host launch
// ---------------------------------------------------------------------------
extern "C" void kernel_launch(void* const* d_in, const int* in_sizes, int n_in,
                              void* d_out, int out_size) {
    (void)in_sizes; (void)n_in; (void)out_size;
    const float*         src  = (const float*)d_in[0];
    const unsigned char* mask = (const unsigned char*)d_in[1];
    const float* Wq = (const float*)d_in[2];  const float* bq = (const float*)d_in[3];
    const float* Wk = (const float*)d_in[4];  const float* bk = (const float*)d_in[5];
    const float* Wv = (const float*)d_in[6];  const float* bv = (const float*)d_in[7];
    const float* Wo = (const float*)d_in[8];  const float* bo = (const float*)d_in[9];
    const float* W1 = (const float*)d_in[10]; const float* b1 = (const float*)d_in[11];
    const float* W2 = (const float*)d_in[12]; const float* b2 = (const float*)d_in[13];
    const float* g1 = (const float*)d_in[14]; const float* be1 = (const float*)d_in[15];
    const float* g2 = (const float*)d_in[16]; const float* be2 = (const float*)d_in[17];
    float* out = (float*)d_out;

    float *h, *q, *k, *v, *sc, *attn, *x1, *ff1, *mb;
    cudaGetSymbolAddress((void**)&h,    g_h);
    cudaGetSymbolAddress((void**)&q,    g_q);
    cudaGetSymbolAddress((void**)&k,    g_k);
    cudaGetSymbolAddress((void**)&v,    g_v);
    cudaGetSymbolAddress((void**)&sc,   g_sc);
    cudaGetSymbolAddress((void**)&attn, g_attn);
    cudaGetSymbolAddress((void**)&x1,   g_x1);
    cudaGetSymbolAddress((void**)&ff1,  g_ff1);
    cudaGetSymbolAddress((void**)&mb,   g_maskbias);

    // 0. Normalize mask encoding -> additive bias
    mask_prep_kernel<<<1, 1024>>>(mask, mb);

    // 1. LN1
    ln_kernel<<<Mrows, 256>>>(src, g1, be1, h);

    // 2. Q/K/V projections: [4096,1024] = h @ W + b
    gemm_kernel<128,128,8,8,8,false,0,0><<<dim3(Dc/128, Mrows/128, 1), 256>>>(
        h, Wq, bq, nullptr, q, Mrows, Dc, Dc, Dc, Dc, Dc, 1.f);
    gemm_kernel<128,128,8,8,8,false,0,0><<<dim3(Dc/128, Mrows/128, 1), 256>>>(
        h, Wk, bk, nullptr, k, Mrows, Dc, Dc, Dc, Dc, Dc, 1.f);
    gemm_kernel<128,128,8,8,8,false,0,0><<<dim3(Dc/128, Mrows/128, 1), 256>>>(
        h, Wv, bv, nullptr, v, Mrows, Dc, Dc, Dc, Dc, Dc, 1.f);

    // 3. scores = Q @ K^T * scale + rel_bias  (per b,h batch)
    gemm_kernel<128,128,8,8,8,true,3,1><<<dim3(Sc/128, Sc/128, Bc*Hc), 256>>>(
        q, k, nullptr, nullptr, sc, Sc, Sc, HDc, Dc, Dc, Sc, 0.125f);

    // 4. softmax with key-padding mask
    softmax_kernel<<<Bc*Hc*Sc, 256>>>(sc, mb);

    // 5. attn = softmax @ V  (per b,h batch), N = HD = 64
    gemm_kernel<128,64,8,8,4,false,0,2><<<dim3(1, Sc/128, Bc*Hc), 256>>>(
        sc, v, nullptr, nullptr, attn, Sc, HDc, Sc, Sc, Dc, Dc, 1.f);

    // 6. x1 = src + attn @ Wo + bo
    gemm_kernel<128,128,8,8,8,false,1,0><<<dim3(Dc/128, Mrows/128, 1), 256>>>(
        attn, Wo, bo, src, x1, Mrows, Dc, Dc, Dc, Dc, Dc, 1.f);

    // 7. LN2 (reuse h)
    ln_kernel<<<Mrows, 256>>>(x1, g2, be2, h);

    // 8. ff1 = gelu(h @ W1 + b1) : [4096, 4096]
    gemm_kernel<128,128,8,8,8,false,2,0><<<dim3(Fc/128, Mrows/128, 1), 256>>>(
        h, W1, b1, nullptr, ff1, Mrows, Fc, Dc, Dc, Fc, Fc, 1.f);

    // 9. out = x1 + ff1 @ W2 + b2
    gemm_kernel<128,128,8,8,8,false,1,0><<<dim3(Dc/128, Mrows/128, 1), 256>>>(
        ff1, W2, b2, x1, out, Mrows, Dc, Fc, Fc, Dc, Dc, 1.f);
}

// round 4
// speedup vs baseline: 3.3487x; 3.3487x over previous
#include <cuda_runtime.h>
#include <cuda_bf16.h>
#include <math.h>
#include <stdint.h>

// ---------------------------------------------------------------------------
// Shape: B=4, S=1024, D=1024, H=16, HD=64, F=4096
// ---------------------------------------------------------------------------
static constexpr int Bc = 4;
static constexpr int Sc = 1024;
static constexpr int Dc = 1024;
static constexpr int Hc = 16;
static constexpr int Fc = 4096;
static constexpr int Mrows = Bc * Sc;                  // 4096
static constexpr long long SD = (long long)Sc * Dc;    // per-batch slice

// ---------------------------------------------------------------------------
// Scratch (__device__ globals: allocation-free, graph-capture safe)
// ---------------------------------------------------------------------------
__device__ __nv_bfloat16 g_h_hi [Mrows * Dc], g_h_lo [Mrows * Dc];
__device__ __nv_bfloat16 g_q_hi [Mrows * Dc], g_q_lo [Mrows * Dc];
__device__ __nv_bfloat16 g_k_hi [Mrows * Dc], g_k_lo [Mrows * Dc];
__device__ __nv_bfloat16 g_v_hi [Mrows * Dc], g_v_lo [Mrows * Dc];
__device__ __nv_bfloat16 g_vt_hi[Mrows * Dc], g_vt_lo[Mrows * Dc];   // [B,H,64,S]
__device__ float         g_sc  [(long long)Bc * Hc * Sc * Sc];        // 256 MB
__device__ __nv_bfloat16 g_p_hi[Bc * Hc * Sc * Sc], g_p_lo[Bc * Hc * Sc * Sc];
__device__ __nv_bfloat16 g_at_hi[Mrows * Dc], g_at_lo[Mrows * Dc];
__device__ float         g_x1  [Mrows * Dc];
__device__ __nv_bfloat16 g_h2_hi[Mrows * Dc], g_h2_lo[Mrows * Dc];
__device__ __nv_bfloat16 g_f1_hi[Mrows * Fc], g_f1_lo[Mrows * Fc];
// transposed+split weights [N,K]
__device__ __nv_bfloat16 g_wq_hi[Dc*Dc], g_wq_lo[Dc*Dc];
__device__ __nv_bfloat16 g_wk_hi[Dc*Dc], g_wk_lo[Dc*Dc];
__device__ __nv_bfloat16 g_wv_hi[Dc*Dc], g_wv_lo[Dc*Dc];
__device__ __nv_bfloat16 g_wo_hi[Dc*Dc], g_wo_lo[Dc*Dc];
__device__ __nv_bfloat16 g_w1_hi[Dc*Fc], g_w1_lo[Dc*Fc];
__device__ __nv_bfloat16 g_w2_hi[Fc*Dc], g_w2_lo[Fc*Dc];
__device__ float g_maskbias[Bc * Sc];

// ---------------------------------------------------------------------------
// sm_80-compatible primitives (valid in compute_100 PTX)
// ---------------------------------------------------------------------------
__device__ __forceinline__ void cp16(uint32_t dst, const void* src) {
    asm volatile("cp.async.cg.shared.global [%0], [%1], 16;" :: "r"(dst), "l"(src));
}
__device__ __forceinline__ void ldsm4(uint32_t* r, uint32_t addr) {
    asm volatile("ldmatrix.sync.aligned.m8n8.x4.shared.b16 {%0,%1,%2,%3}, [%4];"
        : "=r"(r[0]), "=r"(r[1]), "=r"(r[2]), "=r"(r[3]) : "r"(addr));
}
__device__ __forceinline__ void mma_bf16(float* d, const uint32_t* a, const uint32_t* b) {
    asm volatile(
        "mma.sync.aligned.m16n8k16.row.col.f32.bf16.bf16.f32 "
        "{%0,%1,%2,%3}, {%4,%5,%6,%7}, {%8,%9}, {%0,%1,%2,%3};"
        : "+f"(d[0]), "+f"(d[1]), "+f"(d[2]), "+f"(d[3])
        : "r"(a[0]), "r"(a[1]), "r"(a[2]), "r"(a[3]), "r"(b[0]), "r"(b[1]));
}

// ---------------------------------------------------------------------------
// helpers
// ---------------------------------------------------------------------------
__device__ __forceinline__ void split_bf16(float f, __nv_bfloat16& hi, __nv_bfloat16& lo) {
    hi = __float2bfloat16(f);
    lo = __float2bfloat16(f - __bfloat162float(hi));
}
__device__ __forceinline__ float gelu_exact(float x) {
    return 0.5f * x * (1.0f + erff(x * 0.7071067811865475f));
}
__device__ __forceinline__ float warp_sum(float v) {
    #pragma unroll
    for (int o = 16; o > 0; o >>= 1) v += __shfl_xor_sync(0xFFFFFFFFu, v, o);
    return v;
}
__device__ __forceinline__ float warp_max(float v) {
    #pragma unroll
    for (int o = 16; o > 0; o >>= 1) v = fmaxf(v, __shfl_xor_sync(0xFFFFFFFFu, v, o));
    return v;
}

// ---------------------------------------------------------------------------
// mask normalization (encoding auto-detect: int32 / float32 / bool8)
// ---------------------------------------------------------------------------
__global__ void mask_prep_kernel(const unsigned char* __restrict__ m,
                                 float* __restrict__ bias) {
    __shared__ int s_not_i32, s_not_f32;
    if (threadIdx.x == 0) { s_not_i32 = 0; s_not_f32 = 0; }
    __syncthreads();
    for (int i = threadIdx.x; i < Bc * Sc; i += blockDim.x)
        if ((i & 3) != 0 && m[i] != 0) s_not_i32 = 1;
    const unsigned int* w = (const unsigned int*)m;
    for (int i = threadIdx.x; i < (Bc * Sc) / 4; i += blockDim.x) {
        unsigned int x = w[i];
        if (x != 0u && x != 0x3F800000u) s_not_f32 = 1;
    }
    __syncthreads();
    const bool is_i32 = !s_not_i32;
    const bool is_f32 = !is_i32 && !s_not_f32;
    for (int i = threadIdx.x; i < Bc * Sc; i += blockDim.x) {
        int mv;
        if (is_i32)      mv = ((const int*)m)[i];
        else if (is_f32) mv = (((const unsigned int*)m)[i] != 0u);
        else             mv = (int)m[i];
        bias[i] = mv ? -3.0e38f : 0.0f;
    }
}

// ---------------------------------------------------------------------------
// LayerNorm -> bf16 hi/lo pair
// ---------------------------------------------------------------------------
__global__ void ln_kernel(const float* __restrict__ x,
                          const float* __restrict__ g,
                          const float* __restrict__ beta,
                          __nv_bfloat16* __restrict__ yhi,
                          __nv_bfloat16* __restrict__ ylo) {
    const int row = blockIdx.x;
    const float* xr = x + (size_t)row * Dc;
    float v[4], s = 0.f, sq = 0.f;
    #pragma unroll
    for (int i = 0; i < 4; i++) {
        float t = xr[threadIdx.x + i * 256];
        v[i] = t; s += t; sq += t * t;
    }
    __shared__ float sh[2][8];
    s = warp_sum(s); sq = warp_sum(sq);
    const int wid = threadIdx.x >> 5, lid = threadIdx.x & 31;
    if (lid == 0) { sh[0][wid] = s; sh[1][wid] = sq; }
    __syncthreads();
    if (wid == 0) {
        float a  = (lid < 8) ? sh[0][lid] : 0.f;
        float b2 = (lid < 8) ? sh[1][lid] : 0.f;
        a = warp_sum(a); b2 = warp_sum(b2);
        if (lid == 0) { sh[0][0] = a; sh[1][0] = b2; }
    }
    __syncthreads();
    const float mu   = sh[0][0] * (1.f / Dc);
    const float var  = sh[1][0] * (1.f / Dc) - mu * mu;
    const float rstd = rsqrtf(var + 1e-5f);
    #pragma unroll
    for (int i = 0; i < 4; i++) {
        int c = threadIdx.x + i * 256;
        float f = (v[i] - mu) * rstd * g[c] + beta[c];
        __nv_bfloat16 hi, lo; split_bf16(f, hi, lo);
        yhi[(size_t)row * Dc + c] = hi;
        ylo[(size_t)row * Dc + c] = lo;
    }
}

// ---------------------------------------------------------------------------
// Softmax (fp32 scores + mask bias -> bf16 hi/lo probabilities)
// ---------------------------------------------------------------------------
__global__ void softmax_kernel(const float* __restrict__ sc,
                               const float* __restrict__ maskbias,
                               __nv_bfloat16* __restrict__ phi,
                               __nv_bfloat16* __restrict__ plo) {
    const long long row = blockIdx.x;                  // 0 .. B*H*S-1
    const int b = (int)(row / ((long long)Hc * Sc));
    const float* p = sc + row * Sc;
    const float* mrow = maskbias + (size_t)b * Sc;

    float v[4], mx = -3.0e38f;
    #pragma unroll
    for (int i = 0; i < 4; i++) {
        int c = threadIdx.x + i * 256;
        float t = p[c] + mrow[c];
        v[i] = t; mx = fmaxf(mx, t);
    }
    __shared__ float sh[8];
    mx = warp_max(mx);
    const int wid = threadIdx.x >> 5, lid = threadIdx.x & 31;
    if (lid == 0) sh[wid] = mx;
    __syncthreads();
    if (wid == 0) {
        float a = (lid < 8) ? sh[lid] : -3.0e38f;
        a = warp_max(a);
        if (lid == 0) sh[0] = a;
    }
    __syncthreads();
    const float M = sh[0];
    float s = 0.f;
    #pragma unroll
    for (int i = 0; i < 4; i++) {
        float e = (v[i] <= -1.0e38f) ? 0.f : __expf(v[i] - M);
        v[i] = e; s += e;
    }
    __syncthreads();
    s = warp_sum(s);
    if (lid == 0) sh[wid] = s;
    __syncthreads();
    if (wid == 0) {
        float a = (lid < 8) ? sh[lid] : 0.f;
        a = warp_sum(a);
        if (lid == 0) sh[0] = a;
    }
    __syncthreads();
    const float inv = 1.f / sh[0];
    #pragma unroll
    for (int i = 0; i < 4; i++) {
        int c = threadIdx.x + i * 256;
        float f = v[i] * inv;
        __nv_bfloat16 hi, lo; split_bf16(f, hi, lo);
        phi[row * Sc + c] = hi;
        plo[row * Sc + c] = lo;
    }
}

// ---------------------------------------------------------------------------
// Weight transpose + split: W fp32 [K,N] -> T hi/lo bf16 [N,K]
// ---------------------------------------------------------------------------
__global__ void wtrans_kernel(const float* __restrict__ W,
                              __nv_bfloat16* __restrict__ Thi,
                              __nv_bfloat16* __restrict__ Tlo,
                              int K, int N) {
    __shared__ float t[32][33];
    const int n0 = blockIdx.x * 32, k0 = blockIdx.y * 32;
    const int tx = threadIdx.x, ty = threadIdx.y;      // (32, 8)
    #pragma unroll
    for (int i = 0; i < 4; i++)
        t[ty + 8 * i][tx] = W[(size_t)(k0 + ty + 8 * i) * N + n0 + tx];
    __syncthreads();
    #pragma unroll
    for (int i = 0; i < 4; i++) {
        float f = t[tx][ty + 8 * i];
        __nv_bfloat16 hi, lo; split_bf16(f, hi, lo);
        size_t o = (size_t)(n0 + ty + 8 * i) * K + k0 + tx;
        Thi[o] = hi; Tlo[o] = lo;
    }
}

// ---------------------------------------------------------------------------
// V transpose per head: v [B*S, D] bf16 pair -> vt [B,H,64,S] bf16 pair
// ---------------------------------------------------------------------------
__global__ void vtrans_kernel(const __nv_bfloat16* __restrict__ vh,
                              const __nv_bfloat16* __restrict__ vl,
                              __nv_bfloat16* __restrict__ th,
                              __nv_bfloat16* __restrict__ tl) {
    __shared__ __nv_bfloat16 t0[32][33], t1[32][33];
    const int z = blockIdx.z;                      // b*16+h
    const int b = z >> 4, h = z & 15;
    const int s0 = blockIdx.x * 32, d0 = blockIdx.y * 32;
    const int tx = threadIdx.x, ty = threadIdx.y;  // (32, 8)
    const size_t ib = (size_t)b * SD + (size_t)h * 64;
    #pragma unroll
    for (int i = 0; i < 4; i++) {
        size_t o = ib + (size_t)(s0 + ty + 8 * i) * Dc + d0 + tx;
        t0[ty + 8 * i][tx] = vh[o];
        t1[ty + 8 * i][tx] = vl[o];
    }
    __syncthreads();
    #pragma unroll
    for (int i = 0; i < 4; i++) {
        size_t o = ((size_t)z * 64 + d0 + ty + 8 * i) * Sc + s0 + tx;
        th[o] = t0[tx][ty + 8 * i];
        tl[o] = t1[tx][ty + 8 * i];
    }
}

// ---------------------------------------------------------------------------
// mma.sync split-bf16 GEMM.  C(128 x BN) = 3-term split over K.
// EPI: 0=bias+split-out, 1=scores(scale+relbias fp32), 2=split-out,
//      3=bias+residual fp32, 4=bias+gelu+split-out
// MODE: 0 plain; 1 scores (A=Q slice, B=K slice, C=g_sc); 2 attnV
// ---------------------------------------------------------------------------
#define E_SPLIT_BIAS 0
#define E_SCORES     1
#define E_SPLIT      2
#define E_BIAS_RES   3
#define E_GELU_SPLIT 4

template<int BN, int EPI, int MODE>
__global__ void __launch_bounds__(256) gemm_mma(
    const __nv_bfloat16* __restrict__ Ahi, const __nv_bfloat16* __restrict__ Alo,
    const __nv_bfloat16* __restrict__ Bhi, const __nv_bfloat16* __restrict__ Blo,
    const float* __restrict__ bias, const float* __restrict__ res,
    float* __restrict__ Cf,
    __nv_bfloat16* __restrict__ Chi, __nv_bfloat16* __restrict__ Clo,
    int Kdim, int lda, int ldb, int ldc)
{
    constexpr int BM = 128;
    constexpr int WN  = BN / 2;        // warp n-tile (4x2 warp grid)
    constexpr int NFR = WN / 8;        // n-fragments per warp (8 or 4)
    constexpr int RS  = 80;            // padded smem row stride (bytes) per 32-k row

    __shared__ char smA[2][BM * RS];
    __shared__ char smB[2][BN * RS];

    const int tid  = threadIdx.x;
    const int wid  = tid >> 5, lane = tid & 31;
    const int wm   = wid & 3, wn = wid >> 2;
    const int row0 = blockIdx.y * BM;
    const int col0 = blockIdx.x * BN;
    const int z    = blockIdx.z;

    const __nv_bfloat16 *pAh, *pAl, *pBh, *pBl;
    if (MODE == 0) {
        pAh = Ahi + (size_t)row0 * lda; pAl = Alo + (size_t)row0 * lda;
        pBh = Bhi + (size_t)col0 * ldb; pBl = Blo + (size_t)col0 * ldb;
    } else if (MODE == 1) {
        const int b = z >> 4, h = z & 15;
        const size_t ao = (size_t)b * SD + (size_t)h * 64 + (size_t)row0 * Dc;
        const size_t bo = (size_t)b * SD + (size_t)h * 64 + (size_t)col0 * Dc;
        pAh = Ahi + ao; pAl = Alo + ao; pBh = Bhi + bo; pBl = Blo + bo;
    } else {
        const size_t ao = (size_t)z * Sc * Sc + (size_t)row0 * Sc;
        const size_t bo = (size_t)z * 64 * Sc;
        pAh = Ahi + ao; pAl = Alo + ao; pBh = Bhi + bo; pBl = Blo + bo;
    }

    const uint32_t sA = (uint32_t)__cvta_generic_to_shared(&smA[0][0]);
    const uint32_t sB = (uint32_t)__cvta_generic_to_shared(&smB[0][0]);
    const int NCk = Kdim >> 5;
    const int NC3 = 3 * NCk;

    float acc[2][NFR][4];
    #pragma unroll
    for (int a = 0; a < 2; a++)
        #pragma unroll
        for (int b = 0; b < NFR; b++)
            #pragma unroll
            for (int c = 0; c < 4; c++) acc[a][b][c] = 0.f;

    auto issue = [&](int c) {
        const int phase = c / NCk, kc = c - phase * NCk;
        const __nv_bfloat16* sa = (phase == 2 ? pAl : pAh) + kc * 32;
        const __nv_bfloat16* sb = (phase == 1 ? pBl : pBh) + kc * 32;
        const int buf = c & 1;
        #pragma unroll
        for (int i = 0; i < (BM * 4) / 256; i++) {
            const int idx = tid + 256 * i, r = idx >> 2, vv = idx & 3;
            cp16(sA + buf * BM * RS + r * RS + vv * 16, sa + (size_t)r * lda + vv * 8);
        }
        #pragma unroll
        for (int i = 0; i < (BN * 4) / 256; i++) {
            const int idx = tid + 256 * i, r = idx >> 2, vv = idx & 3;
            cp16(sB + buf * BN * RS + r * RS + vv * 16, sb + (size_t)r * ldb + vv * 8);
        }
        asm volatile("cp.async.commit_group;" ::: "memory");
    };

    issue(0);
    for (int c = 0; c < NC3; c++) {
        if (c + 1 < NC3) {
            issue(c + 1);
            asm volatile("cp.async.wait_group 1;" ::: "memory");
        } else {
            asm volatile("cp.async.wait_group 0;" ::: "memory");
        }
        __syncthreads();
        const int buf = c & 1;
        const uint32_t ab = sA + buf * BM * RS;
        const uint32_t bb = sB + buf * BN * RS;
        #pragma unroll
        for (int ks = 0; ks < 2; ks++) {
            uint32_t afr[2][4];
            #pragma unroll
            for (int mf = 0; mf < 2; mf++) {
                const int row = wm * 32 + mf * 16 + (lane & 15);
                const int ko  = ks * 16 + ((lane >> 4) << 3);
                ldsm4(afr[mf], ab + row * RS + ko * 2);
            }
            uint32_t bfr[NFR][2];
            #pragma unroll
            for (int p = 0; p < NFR / 2; p++) {
                const int n  = wn * WN + p * 16 + (lane & 7) + ((lane >> 4) << 3);
                const int ko = ks * 16 + (((lane >> 3) & 1) << 3);
                uint32_t r4[4];
                ldsm4(r4, bb + n * RS + ko * 2);
                bfr[2*p][0] = r4[0]; bfr[2*p][1] = r4[1];
                bfr[2*p+1][0] = r4[2]; bfr[2*p+1][1] = r4[3];
            }
            #pragma unroll
            for (int mf = 0; mf < 2; mf++)
                #pragma unroll
                for (int nf = 0; nf < NFR; nf++)
                    mma_bf16(acc[mf][nf], afr[mf], bfr[nf]);
        }
        __syncthreads();
    }

    // ---- epilogue ----
    #pragma unroll
    for (int mf = 0; mf < 2; mf++)
        #pragma unroll
        for (int nf = 0; nf < NFR; nf++)
            #pragma unroll
            for (int r = 0; r < 4; r++) {
                const int gm = row0 + wm * 32 + mf * 16 + (lane >> 2) + ((r >> 1) << 3);
                const int gn = col0 + wn * WN + nf * 8 + ((lane & 3) << 1) + (r & 1);
                float f = acc[mf][nf][r];
                if (EPI == E_SCORES) {
                    f = f * 0.125f - 0.1f * fabsf((float)(gm - gn));
                    Cf[(size_t)z * Sc * Sc + (size_t)gm * Sc + gn] = f;
                } else if (EPI == E_BIAS_RES) {
                    f += bias[gn] + res[(size_t)gm * ldc + gn];
                    Cf[(size_t)gm * ldc + gn] = f;
                } else {
                    if (EPI == E_SPLIT_BIAS) f += bias[gn];
                    if (EPI == E_GELU_SPLIT) f = gelu_exact(f + bias[gn]);
                    size_t o;
                    if (MODE == 2) {
                        const int b = z >> 4, h = z & 15;
                        o = (size_t)b * SD + (size_t)h * 64 + (size_t)gm * Dc + gn;
                    } else {
                        o = (size_t)gm * ldc + gn;
                    }
                    __nv_bfloat16 hi, lo; split_bf16(f, hi, lo);
                    Chi[o] = hi; Clo[o] = lo;
                }
            }
}

// ---------------------------------------------------------------------------
// Host launch
// ---------------------------------------------------------------------------
extern "C" void kernel_launch(void* const* d_in, const int* in_sizes, int n_in,
                              void* d_out, int out_size) {
    (void)in_sizes; (void)n_in; (void)out_size;
    const float*         src  = (const float*)d_in[0];
    const unsigned char* mask = (const unsigned char*)d_in[1];
    const float* Wq = (const float*)d_in[2];  const float* bq = (const float*)d_in[3];
    const float* Wk = (const float*)d_in[4];  const float* bk = (const float*)d_in[5];
    const float* Wv = (const float*)d_in[6];  const float* bv = (const float*)d_in[7];
    const float* Wo = (const float*)d_in[8];  const float* bo = (const float*)d_in[9];
    const float* W1 = (const float*)d_in[10]; const float* b1 = (const float*)d_in[11];
    const float* W2 = (const float*)d_in[12]; const float* b2 = (const float*)d_in[13];
    const float* g1 = (const float*)d_in[14]; const float* be1 = (const float*)d_in[15];
    const float* g2 = (const float*)d_in[16]; const float* be2 = (const float*)d_in[17];
    float* out = (float*)d_out;

    #define SYM(T, name, sym) T* name; cudaGetSymbolAddress((void**)&name, sym)
    SYM(__nv_bfloat16, hhi, g_h_hi);  SYM(__nv_bfloat16, hlo, g_h_lo);
    SYM(__nv_bfloat16, qhi, g_q_hi);  SYM(__nv_bfloat16, qlo, g_q_lo);
    SYM(__nv_bfloat16, khi, g_k_hi);  SYM(__nv_bfloat16, klo, g_k_lo);
    SYM(__nv_bfloat16, vhi, g_v_hi);  SYM(__nv_bfloat16, vlo, g_v_lo);
    SYM(__nv_bfloat16, vthi, g_vt_hi); SYM(__nv_bfloat16, vtlo, g_vt_lo);
    SYM(float, sc, g_sc);
    SYM(__nv_bfloat16, phi, g_p_hi);  SYM(__nv_bfloat16, plo, g_p_lo);
    SYM(__nv_bfloat16, athi, g_at_hi); SYM(__nv_bfloat16, atlo, g_at_lo);
    SYM(float, x1, g_x1);
    SYM(__nv_bfloat16, h2hi, g_h2_hi); SYM(__nv_bfloat16, h2lo, g_h2_lo);
    SYM(__nv_bfloat16, f1hi, g_f1_hi); SYM(__nv_bfloat16, f1lo, g_f1_lo);
    SYM(__nv_bfloat16, wqh, g_wq_hi); SYM(__nv_bfloat16, wql, g_wq_lo);
    SYM(__nv_bfloat16, wkh, g_wk_hi); SYM(__nv_bfloat16, wkl, g_wk_lo);
    SYM(__nv_bfloat16, wvh, g_wv_hi); SYM(__nv_bfloat16, wvl, g_wv_lo);
    SYM(__nv_bfloat16, woh, g_wo_hi); SYM(__nv_bfloat16, wol, g_wo_lo);
    SYM(__nv_bfloat16, w1h, g_w1_hi); SYM(__nv_bfloat16, w1l, g_w1_lo);
    SYM(__nv_bfloat16, w2h, g_w2_hi); SYM(__nv_bfloat16, w2l, g_w2_lo);
    SYM(float, mb, g_maskbias);
    #undef SYM

    const dim3 tb(32, 8);

    // 0. mask + weight prep
    mask_prep_kernel<<<1, 1024>>>(mask, mb);
    wtrans_kernel<<<dim3(Dc/32, Dc/32), tb>>>(Wq, wqh, wql, Dc, Dc);
    wtrans_kernel<<<dim3(Dc/32, Dc/32), tb>>>(Wk, wkh, wkl, Dc, Dc);
    wtrans_kernel<<<dim3(Dc/32, Dc/32), tb>>>(Wv, wvh, wvl, Dc, Dc);
    wtrans_kernel<<<dim3(Dc/32, Dc/32), tb>>>(Wo, woh, wol, Dc, Dc);
    wtrans_kernel<<<dim3(Fc/32, Dc/32), tb>>>(W1, w1h, w1l, Dc, Fc);
    wtrans_kernel<<<dim3(Dc/32, Fc/32), tb>>>(W2, w2h, w2l, Fc, Dc);

    // 1. LN1 -> h pair
    ln_kernel<<<Mrows, 256>>>(src, g1, be1, hhi, hlo);

    // 2. Q/K/V projections (M=4096, N=1024, K=1024)
    gemm_mma<128, E_SPLIT_BIAS, 0><<<dim3(Dc/128, Mrows/128, 1), 256>>>(
        hhi, hlo, wqh, wql, bq, nullptr, nullptr, qhi, qlo, Dc, Dc, Dc, Dc);
    gemm_mma<128, E_SPLIT_BIAS, 0><<<dim3(Dc/128, Mrows/128, 1), 256>>>(
        hhi, hlo, wkh, wkl, bk, nullptr, nullptr, khi, klo, Dc, Dc, Dc, Dc);
    gemm_mma<128, E_SPLIT_BIAS, 0><<<dim3(Dc/128, Mrows/128, 1), 256>>>(
        hhi, hlo, wvh, wvl, bv, nullptr, nullptr, vhi, vlo, Dc, Dc, Dc, Dc);

    // 3. V transpose per head
    vtrans_kernel<<<dim3(Sc/32, 2, Bc*Hc), tb>>>(vhi, vlo, vthi, vtlo);

    // 4. scores = scale*Q@K^T + relbias  (K=64 per head)
    gemm_mma<128, E_SCORES, 1><<<dim3(Sc/128, Sc/128, Bc*Hc), 256>>>(
        qhi, qlo, khi, klo, nullptr, nullptr, sc, nullptr, nullptr, 64, Dc, Dc, Sc);

    // 5. softmax -> p pair
    softmax_kernel<<<Bc*Hc*Sc, 256>>>(sc, mb, phi, plo);

    // 6. attn = P @ V  (per head, N=64, K=1024)
    gemm_mma<64, E_SPLIT, 2><<<dim3(1, Sc/128, Bc*Hc), 256>>>(
        phi, plo, vthi, vtlo, nullptr, nullptr, nullptr, athi, atlo, Sc, Sc, Sc, Dc);

    // 7. x1 = src + attn @ Wo + bo
    gemm_mma<128, E_BIAS_RES, 0><<<dim3(Dc/128, Mrows/128, 1), 256>>>(
        athi, atlo, woh, wol, bo, src, x1, nullptr, nullptr, Dc, Dc, Dc, Dc);

    // 8. LN2 -> h2 pair
    ln_kernel<<<Mrows, 256>>>(x1, g2, be2, h2hi, h2lo);

    // 9. ff1 = gelu(h2 @ W1 + b1)  (N=4096)
    gemm_mma<128, E_GELU_SPLIT, 0><<<dim3(Fc/128, Mrows/128, 1), 256>>>(
        h2hi, h2lo, w1h, w1l, b1, nullptr, nullptr, f1hi, f1lo, Dc, Dc, Dc, Fc);

    // 10. out = x1 + ff1 @ W2 + b2  (K=4096)
    gemm_mma<128, E_BIAS_RES, 0><<<dim3(Dc/128, Mrows/128, 1), 256>>>(
        f1hi, f1lo, w2h, w2l, b2, x1, out, nullptr, nullptr, Fc, Fc, Fc, Dc);
}